// round 2
// baseline (speedup 1.0000x reference)
#include <cuda_runtime.h>
#include <cuda_bf16.h>

#define GG   256      // graphs
#define DD   128      // feature dim
#define ROWS_PER_WARP 256
#define ACC_THREADS   256   // 8 warps per CTA

__device__ float g_sums[GG * DD];
__device__ float g_counts[GG];
__device__ int   g_is64;

__device__ __forceinline__ int load_g(const void* batch, long long i, int is64) {
    if (is64) return (int)((const long long*)batch)[i];
    return ((const int*)batch)[i];
}

// Kernel 0: zero scratch + detect batch dtype.
// If batch is int64: int32 word (N-1) is the HIGH word of element (N-2)/2 -> 0.
// If batch is int32: word (N-1) is the last (sorted, max) value -> ~255 (>0).
__global__ void zero_detect_kernel(const void* __restrict__ batch, int N) {
    int i = blockIdx.x * blockDim.x + threadIdx.x;
    if (i < GG * DD) g_sums[i] = 0.0f;
    if (i < GG)      g_counts[i] = 0.0f;
    if (i == 0)      g_is64 = (((const int*)batch)[N - 1] == 0) ? 1 : 0;
}

__device__ __forceinline__ void flush_seg(int g, float4 acc, int cnt, int lane) {
    if (cnt == 0) return;
    float* s = g_sums + (long long)g * DD + lane * 4;
    atomicAdd(s + 0, acc.x);
    atomicAdd(s + 1, acc.y);
    atomicAdd(s + 2, acc.z);
    atomicAdd(s + 3, acc.w);
    if (lane == 0) atomicAdd(&g_counts[g], (float)cnt);
}

// Kernel 1: streaming segment-sum. One warp owns ROWS_PER_WARP contiguous rows.
// lane l accumulates columns [4l, 4l+4) of the running segment in a float4.
__global__ void accum_kernel(const float4* __restrict__ x4,
                             const void* __restrict__ batch, int N) {
    const int is64 = g_is64;
    const int lane = threadIdx.x & 31;
    const long long warp = (long long)(blockIdx.x * (ACC_THREADS / 32)) + (threadIdx.x >> 5);
    long long r0 = warp * ROWS_PER_WARP;
    if (r0 >= N) return;
    long long r1 = r0 + ROWS_PER_WARP;
    if (r1 > N) r1 = N;

    float4 acc = make_float4(0.f, 0.f, 0.f, 0.f);
    int cnt = 0;
    int cur = load_g(batch, r0, is64);

    long long r = r0;
    for (; r + 4 <= r1; r += 4) {
        int ga = load_g(batch, r,     is64);
        int gd = load_g(batch, r + 3, is64);
        // issue all 4 row loads before any branching -> MLP=4
        float4 v0 = x4[(r    ) * 32 + lane];
        float4 v1 = x4[(r + 1) * 32 + lane];
        float4 v2 = x4[(r + 2) * 32 + lane];
        float4 v3 = x4[(r + 3) * 32 + lane];
        if (ga == cur && gd == cur) {   // sorted => all 4 rows in current segment
            acc.x += (v0.x + v1.x) + (v2.x + v3.x);
            acc.y += (v0.y + v1.y) + (v2.y + v3.y);
            acc.z += (v0.z + v1.z) + (v2.z + v3.z);
            acc.w += (v0.w + v1.w) + (v2.w + v3.w);
            cnt += 4;
        } else {                        // segment boundary inside this quad (rare)
            int gs[4];
            gs[0] = ga;
            gs[1] = load_g(batch, r + 1, is64);
            gs[2] = load_g(batch, r + 2, is64);
            gs[3] = gd;
            float4 vs[4] = {v0, v1, v2, v3};
            #pragma unroll
            for (int k = 0; k < 4; k++) {
                if (gs[k] != cur) {
                    flush_seg(cur, acc, cnt, lane);
                    acc = make_float4(0.f, 0.f, 0.f, 0.f);
                    cnt = 0;
                    cur = gs[k];
                }
                acc.x += vs[k].x; acc.y += vs[k].y;
                acc.z += vs[k].z; acc.w += vs[k].w;
                cnt++;
            }
        }
    }
    for (; r < r1; r++) {   // tail (last partial warp only)
        int g = load_g(batch, r, is64);
        float4 v = x4[r * 32 + lane];
        if (g != cur) {
            flush_seg(cur, acc, cnt, lane);
            acc = make_float4(0.f, 0.f, 0.f, 0.f);
            cnt = 0;
            cur = g;
        }
        acc.x += v.x; acc.y += v.y; acc.z += v.z; acc.w += v.w;
        cnt++;
    }
    flush_seg(cur, acc, cnt, lane);
}

// Kernel 2: mean + MLP head. One block per graph, 64 threads (one per W1 column).
__global__ void finalize_kernel(const float* __restrict__ W1,
                                const float* __restrict__ b1,
                                const float* __restrict__ W2,
                                const float* __restrict__ b2,
                                float* __restrict__ out) {
    const int g = blockIdx.x;
    const int j = threadIdx.x;           // 0..63
    __shared__ float mean_s[DD];
    __shared__ float red[64];

    float inv = 1.0f / g_counts[g];
    mean_s[j]      = g_sums[g * DD + j]      * inv;
    mean_s[j + 64] = g_sums[g * DD + j + 64] * inv;
    __syncthreads();

    float h = b1[j];
    #pragma unroll
    for (int d = 0; d < DD; d++)
        h = fmaf(mean_s[d], W1[d * 64 + j], h);   // W1 is [128,64] row-major
    h = fmaxf(h, 0.0f);

    red[j] = h * W2[j];
    __syncthreads();
    #pragma unroll
    for (int s = 32; s > 0; s >>= 1) {
        if (j < s) red[j] += red[j + s];
        __syncthreads();
    }
    if (j == 0) out[g] = red[0] + b2[0];
}

extern "C" void kernel_launch(void* const* d_in, const int* in_sizes, int n_in,
                              void* d_out, int out_size) {
    const float* x     = (const float*)d_in[0];
    const void*  batch = d_in[1];
    const float* W1    = (const float*)d_in[2];
    const float* b1    = (const float*)d_in[3];
    const float* W2    = (const float*)d_in[4];
    const float* b2    = (const float*)d_in[5];
    float* out = (float*)d_out;

    const int N = in_sizes[0] / DD;   // 2,000,000

    zero_detect_kernel<<<(GG * DD + 255) / 256, 256>>>(batch, N);

    int warps = (N + ROWS_PER_WARP - 1) / ROWS_PER_WARP;
    int ctas  = (warps + (ACC_THREADS / 32) - 1) / (ACC_THREADS / 32);
    accum_kernel<<<ctas, ACC_THREADS>>>((const float4*)x, batch, N);

    finalize_kernel<<<GG, 64>>>(W1, b1, W2, b2, out);
}

// round 4
// speedup vs baseline: 1.0759x; 1.0759x over previous
#include <cuda_runtime.h>
#include <cuda_bf16.h>

#define GG   256      // graphs
#define DD   128      // feature dim
#define ROWS_PER_WARP 256
#define ACC_THREADS   256   // 8 warps per CTA

// Zero-initialized at module load; finalize_kernel re-zeros after consuming,
// so the invariant "scratch is zero at accum launch" holds on every graph replay.
__device__ float g_sums[GG * DD];
__device__ float g_counts[GG];

__device__ __forceinline__ int load_g(const void* batch, long long i, int is64) {
    if (is64) return (int)((const long long*)batch)[i];
    return ((const int*)batch)[i];
}

__device__ __forceinline__ void flush_seg(int g, float4 acc, int cnt, int lane) {
    if (cnt == 0) return;
    float* s = g_sums + (long long)g * DD + lane * 4;
    atomicAdd(s + 0, acc.x);
    atomicAdd(s + 1, acc.y);
    atomicAdd(s + 2, acc.z);
    atomicAdd(s + 3, acc.w);
    if (lane == 0) atomicAdd(&g_counts[g], (float)cnt);
}

// Streaming segment-sum. One warp owns ROWS_PER_WARP contiguous rows; lane l
// accumulates columns [4l, 4l+4) in a float4.
// batch is sorted, segments avg ~7813 rows >> 256 rows/warp, so ~97% of warps
// take the single-segment fast path: no per-row batch loads, no branches,
// 8 LDG.128 in flight per lane.
__global__ void accum_kernel(const float4* __restrict__ x4,
                             const void* __restrict__ batch, int N) {
    // dtype probe: int32 word N-1 is the high half of int64 element 999,999 (=0)
    // if batch is int64, but the sorted max (>0) if int32. L1-cached, ~free.
    const int is64 = (((const int*)batch)[N - 1] == 0);
    const int lane = threadIdx.x & 31;
    const long long warp = (long long)(blockIdx.x * (ACC_THREADS / 32)) + (threadIdx.x >> 5);
    long long r0 = warp * ROWS_PER_WARP;
    if (r0 >= N) return;
    long long r1 = r0 + ROWS_PER_WARP;
    if (r1 > N) r1 = N;

    const int gfirst = load_g(batch, r0, is64);
    const int glast  = load_g(batch, r1 - 1, is64);

    if (gfirst == glast) {
        // ---- fast path: whole block in one segment ----
        float4 acc = make_float4(0.f, 0.f, 0.f, 0.f);
        long long r = r0;
        for (; r + 8 <= r1; r += 8) {
            float4 v[8];
            #pragma unroll
            for (int k = 0; k < 8; k++)
                v[k] = __ldcs(&x4[(r + k) * 32 + lane]);   // evict-first stream
            #pragma unroll
            for (int k = 0; k < 8; k++) {
                acc.x += v[k].x; acc.y += v[k].y;
                acc.z += v[k].z; acc.w += v[k].w;
            }
        }
        for (; r < r1; r++) {   // only the final partial warp hits this
            float4 v = __ldcs(&x4[r * 32 + lane]);
            acc.x += v.x; acc.y += v.y; acc.z += v.z; acc.w += v.w;
        }
        flush_seg(gfirst, acc, (int)(r1 - r0), lane);
        return;
    }

    // ---- slow path: segment boundary inside this block (~3% of warps) ----
    float4 acc = make_float4(0.f, 0.f, 0.f, 0.f);
    int cnt = 0;
    int cur = gfirst;

    long long r = r0;
    for (; r + 4 <= r1; r += 4) {
        int ga = load_g(batch, r,     is64);
        int gd = load_g(batch, r + 3, is64);
        float4 v0 = __ldcs(&x4[(r    ) * 32 + lane]);
        float4 v1 = __ldcs(&x4[(r + 1) * 32 + lane]);
        float4 v2 = __ldcs(&x4[(r + 2) * 32 + lane]);
        float4 v3 = __ldcs(&x4[(r + 3) * 32 + lane]);
        if (ga == cur && gd == cur) {   // sorted => all 4 rows in current segment
            acc.x += (v0.x + v1.x) + (v2.x + v3.x);
            acc.y += (v0.y + v1.y) + (v2.y + v3.y);
            acc.z += (v0.z + v1.z) + (v2.z + v3.z);
            acc.w += (v0.w + v1.w) + (v2.w + v3.w);
            cnt += 4;
        } else {
            int gs[4];
            gs[0] = ga;
            gs[1] = load_g(batch, r + 1, is64);
            gs[2] = load_g(batch, r + 2, is64);
            gs[3] = gd;
            float4 vs[4] = {v0, v1, v2, v3};
            #pragma unroll
            for (int k = 0; k < 4; k++) {
                if (gs[k] != cur) {
                    flush_seg(cur, acc, cnt, lane);
                    acc = make_float4(0.f, 0.f, 0.f, 0.f);
                    cnt = 0;
                    cur = gs[k];
                }
                acc.x += vs[k].x; acc.y += vs[k].y;
                acc.z += vs[k].z; acc.w += vs[k].w;
                cnt++;
            }
        }
    }
    for (; r < r1; r++) {
        int g = load_g(batch, r, is64);
        float4 v = __ldcs(&x4[r * 32 + lane]);
        if (g != cur) {
            flush_seg(cur, acc, cnt, lane);
            acc = make_float4(0.f, 0.f, 0.f, 0.f);
            cnt = 0;
            cur = g;
        }
        acc.x += v.x; acc.y += v.y; acc.z += v.z; acc.w += v.w;
        cnt++;
    }
    flush_seg(cur, acc, cnt, lane);
}

// Mean + MLP head. One block per graph, 64 threads (one per W1 column).
// Consumes g_sums/g_counts for its graph, then re-zeros them so the next
// graph replay starts from a clean state.
__global__ void finalize_kernel(const float* __restrict__ W1,
                                const float* __restrict__ b1,
                                const float* __restrict__ W2,
                                const float* __restrict__ b2,
                                float* __restrict__ out) {
    const int g = blockIdx.x;
    const int j = threadIdx.x;           // 0..63
    __shared__ float mean_s[DD];
    __shared__ float red[64];

    float cntv = g_counts[g];            // all threads read before thread 0 re-zeros
    float inv = 1.0f / cntv;
    mean_s[j]      = g_sums[g * DD + j]      * inv;
    mean_s[j + 64] = g_sums[g * DD + j + 64] * inv;
    __syncthreads();                     // orders g_counts reads before the re-zero

    // restore zero-invariant for the next replay
    g_sums[g * DD + j]      = 0.0f;
    g_sums[g * DD + j + 64] = 0.0f;
    if (j == 0) g_counts[g] = 0.0f;

    float h = b1[j];
    #pragma unroll
    for (int d = 0; d < DD; d++)
        h = fmaf(mean_s[d], W1[d * 64 + j], h);   // W1 is [128,64] row-major
    h = fmaxf(h, 0.0f);

    red[j] = h * W2[j];
    __syncthreads();
    #pragma unroll
    for (int s = 32; s > 0; s >>= 1) {
        if (j < s) red[j] += red[j + s];
        __syncthreads();
    }
    if (j == 0) out[g] = red[0] + b2[0];
}

extern "C" void kernel_launch(void* const* d_in, const int* in_sizes, int n_in,
                              void* d_out, int out_size) {
    const float* x     = (const float*)d_in[0];
    const void*  batch = d_in[1];
    const float* W1    = (const float*)d_in[2];
    const float* b1    = (const float*)d_in[3];
    const float* W2    = (const float*)d_in[4];
    const float* b2    = (const float*)d_in[5];
    float* out = (float*)d_out;

    const int N = in_sizes[0] / DD;   // 2,000,000

    int warps = (N + ROWS_PER_WARP - 1) / ROWS_PER_WARP;
    int ctas  = (warps + (ACC_THREADS / 32) - 1) / (ACC_THREADS / 32);
    accum_kernel<<<ctas, ACC_THREADS>>>((const float4*)x, batch, N);

    finalize_kernel<<<GG, 64>>>(W1, b1, W2, b2, out);
}